// round 1
// baseline (speedup 1.0000x reference)
#include <cuda_runtime.h>

#define NN   32
#define CC   256
#define TT   128
#define VV   25
#define KK   3
#define MIDC 64
#define KM   192      // KK*MIDC
#define OUTC 256
#define TV   3200     // TT*VV

// ---------------- scratch (device globals; no allocation) ----------------
__device__ float g_tmp[NN * CC * VV];                  // T-mean          0.8 MB
__device__ float g_afull[NN * KM * VV * VV];           // adjacency      15.4 MB
__device__ float g_prex[NN * KM * TV];                 // pre branch     78.6 MB
__device__ float g_y[NN * KM * TV];                    // aggregated     78.6 MB

// ---------------- kernel 1: mean over T ----------------
// grid = NN*CC blocks, 128 threads (4 warps x 32 lanes, lanes 0..24 active)
__global__ void mean_kernel(const float* __restrict__ x) {
    int nc   = blockIdx.x;
    int lane = threadIdx.x & 31;
    int warp = threadIdx.x >> 5;
    __shared__ float red[4][VV];
    const float* base = x + (size_t)nc * (TT * VV);
    if (lane < VV) {
        float s = 0.f;
        for (int t = warp; t < TT; t += 4)
            s += base[t * VV + lane];
        red[warp][lane] = s;
    }
    __syncthreads();
    if (warp == 0 && lane < VV) {
        float tot = red[0][lane] + red[1][lane] + red[2][lane] + red[3][lane];
        g_tmp[nc * VV + lane] = tot * (1.0f / TT);
    }
}

// ---------------- kernel 2: attention / adjacency ----------------
// grid = NN*KK blocks, 256 threads. Computes x1, x2, g, softmax, Afull.
__global__ __launch_bounds__(256) void attn_kernel(
    const float* __restrict__ A,  const float* __restrict__ alpha,
    const float* __restrict__ beta,
    const float* __restrict__ c1w, const float* __restrict__ c1b,
    const float* __restrict__ c2w, const float* __restrict__ c2b)
{
    int nk = blockIdx.x;            // n*KK + k
    int n  = nk / KK, k = nk % KK;
    int tid = threadIdx.x;

    __shared__ float tmp_s[CC * VV];    // 6400
    __shared__ float x1_s[MIDC * VV];   // 1600
    __shared__ float x2_s[MIDC * VV];   // 1600
    __shared__ float g_s[VV * VV];      // 625

    const float* tsrc = g_tmp + n * CC * VV;
    for (int i = tid; i < CC * VV; i += 256) tmp_s[i] = tsrc[i];
    __syncthreads();

    int base = k * MIDC;
    for (int i = tid; i < MIDC * VV; i += 256) {
        int co = i / VV, a = i % VV;
        const float* w1 = c1w + (size_t)(base + co) * CC;
        const float* w2 = c2w + (size_t)(base + co) * CC;
        float a1 = c1b[base + co], a2 = c2b[base + co];
        #pragma unroll 8
        for (int c = 0; c < CC; c++) {
            float tv = tmp_s[c * VV + a];
            a1 = fmaf(w1[c], tv, a1);
            a2 = fmaf(w2[c], tv, a2);
        }
        x1_s[i] = a1;
        x2_s[i] = a2;
    }
    __syncthreads();

    // g[a][b] = sum_c x1[c][a] * x2[c][b]
    for (int i = tid; i < VV * VV; i += 256) {
        int a = i / VV, b = i % VV;
        float acc = 0.f;
        #pragma unroll 8
        for (int c = 0; c < MIDC; c++)
            acc = fmaf(x1_s[c * VV + a], x2_s[c * VV + b], acc);
        g_s[i] = acc;
    }
    __syncthreads();

    // softmax over a (per column b), scaled by beta[k]
    if (tid < VV) {
        int b = tid;
        float m = -1e30f;
        for (int a = 0; a < VV; a++) m = fmaxf(m, g_s[a * VV + b]);
        float ssum = 0.f;
        float e[VV];
        for (int a = 0; a < VV; a++) { e[a] = expf(g_s[a * VV + b] - m); ssum += e[a]; }
        float sc = beta[k] / ssum;
        for (int a = 0; a < VV; a++) g_s[a * VV + b] = e[a] * sc;
    }
    __syncthreads();

    float al = alpha[k];
    const float* Ak = A + k * VV * VV;
    float* outp = g_afull + (size_t)nk * MIDC * VV * VV;
    for (int i = tid; i < MIDC * VV * VV; i += 256) {
        int c = i / (VV * VV), r = i % (VV * VV);
        int a = r / VV, b = r % VV;
        outp[i] = tanhf(x1_s[c * VV + a] - x2_s[c * VV + b]) * al + Ak[r] + g_s[r];
    }
}

// ---------------- GEMM tiling parameters ----------------
#define BM 64
#define BN 128
#define BK 16

// ---------------- kernel 3: pre GEMM + BN + ReLU ----------------
// grid = (TV/BN, KM/BM, NN) ; C[m][col] = relu(s1[m]*(W@X + b) + be)
__global__ __launch_bounds__(256) void gemm_pre_kernel(
    const float* __restrict__ x, const float* __restrict__ w,
    const float* __restrict__ bias, const float* __restrict__ gam,
    const float* __restrict__ be)
{
    int n  = blockIdx.z;
    int m0 = blockIdx.y * BM;
    int c0 = blockIdx.x * BN;
    const float* Xn = x + (size_t)n * CC * TV;

    __shared__ float As[BK][BM];
    __shared__ float Bs[BK][BN];

    int tid  = threadIdx.x;
    int trow = (tid >> 4) * 4;     // 0..60
    int tcol = (tid & 15) * 8;     // 0..120

    float acc[4][8];
    #pragma unroll
    for (int i = 0; i < 4; i++)
        #pragma unroll
        for (int j = 0; j < 8; j++) acc[i][j] = 0.f;

    for (int k0 = 0; k0 < CC; k0 += BK) {
        {   // A tile: 64x16 from w (row-major KMxCC)
            int m  = tid >> 2;
            int k4 = (tid & 3) * 4;
            float4 v = *(const float4*)(w + (size_t)(m0 + m) * CC + k0 + k4);
            As[k4 + 0][m] = v.x; As[k4 + 1][m] = v.y;
            As[k4 + 2][m] = v.z; As[k4 + 3][m] = v.w;
        }
        {   // B tile: 16x128 from Xn (row-major CCxTV)
            int kk = tid >> 5;
            int c4 = (tid & 31) * 4;
            #pragma unroll
            for (int it = 0; it < 2; it++) {
                float4 v = *(const float4*)(Xn + (size_t)(k0 + kk + it * 8) * TV + c0 + c4);
                *(float4*)&Bs[kk + it * 8][c4] = v;
            }
        }
        __syncthreads();
        #pragma unroll
        for (int kk = 0; kk < BK; kk++) {
            float a[4], bb[8];
            *(float4*)a        = *(const float4*)&As[kk][trow];
            *(float4*)bb       = *(const float4*)&Bs[kk][tcol];
            *(float4*)(bb + 4) = *(const float4*)&Bs[kk][tcol + 4];
            #pragma unroll
            for (int i = 0; i < 4; i++)
                #pragma unroll
                for (int j = 0; j < 8; j++)
                    acc[i][j] = fmaf(a[i], bb[j], acc[i][j]);
        }
        __syncthreads();
    }

    const float rs = rsqrtf(1.f + 1e-5f);
    float* On = g_prex + (size_t)n * KM * TV;
    #pragma unroll
    for (int i = 0; i < 4; i++) {
        int m = m0 + trow + i;
        float bi = bias[m], sc = gam[m] * rs, b2 = be[m];
        float vr[8];
        #pragma unroll
        for (int j = 0; j < 8; j++)
            vr[j] = fmaxf((acc[i][j] + bi) * sc + b2, 0.f);
        float* dst = On + (size_t)m * TV + c0 + tcol;
        *(float4*)dst       = *(float4*)vr;
        *(float4*)(dst + 4) = *(float4*)(vr + 4);
    }
}

// ---------------- kernel 4: graph aggregation ----------------
// grid = NN*KM blocks, 128 threads; y[t,u] = sum_v prex[t,v]*Af[u,v]
__global__ __launch_bounds__(128) void agg_kernel() {
    int idx = blockIdx.x;                 // n*KM + k*MIDC + c  (matches both buffers)
    int tid = threadIdx.x;

    __shared__ float Af[VV * VV];
    __shared__ float px[TT * VV];
    __shared__ float ys[TT * VV];

    const float* Afg = g_afull + (size_t)idx * (VV * VV);
    for (int i = tid; i < VV * VV; i += 128) Af[i] = Afg[i];
    const float* pxg = g_prex + (size_t)idx * TV;
    for (int i = tid; i < TV; i += 128) px[i] = pxg[i];
    __syncthreads();

    int t = tid;
    float pr[VV];
    #pragma unroll
    for (int v = 0; v < VV; v++) pr[v] = px[t * VV + v];   // stride-25: conflict-free
    #pragma unroll
    for (int u = 0; u < VV; u++) {
        float accv = 0.f;
        #pragma unroll
        for (int v = 0; v < VV; v++)
            accv = fmaf(pr[v], Af[u * VV + v], accv);      // Af: warp-broadcast
        ys[t * VV + u] = accv;
    }
    __syncthreads();

    float* yg = g_y + (size_t)idx * TV;
    for (int i = tid; i < TV; i += 128) yg[i] = ys[i];
}

// ---------------- kernel 5: post GEMM + BN + residual + ReLU ----------------
__global__ __launch_bounds__(256) void gemm_post_kernel(
    const float* __restrict__ x, const float* __restrict__ w,
    const float* __restrict__ bias, const float* __restrict__ gam,
    const float* __restrict__ bb, float* __restrict__ out)
{
    int n  = blockIdx.z;
    int m0 = blockIdx.y * BM;
    int c0 = blockIdx.x * BN;
    const float* Yn = g_y + (size_t)n * KM * TV;

    __shared__ float As[BK][BM];
    __shared__ float Bs[BK][BN];

    int tid  = threadIdx.x;
    int trow = (tid >> 4) * 4;
    int tcol = (tid & 15) * 8;

    float acc[4][8];
    #pragma unroll
    for (int i = 0; i < 4; i++)
        #pragma unroll
        for (int j = 0; j < 8; j++) acc[i][j] = 0.f;

    for (int k0 = 0; k0 < KM; k0 += BK) {
        {
            int m  = tid >> 2;
            int k4 = (tid & 3) * 4;
            float4 v = *(const float4*)(w + (size_t)(m0 + m) * KM + k0 + k4);
            As[k4 + 0][m] = v.x; As[k4 + 1][m] = v.y;
            As[k4 + 2][m] = v.z; As[k4 + 3][m] = v.w;
        }
        {
            int kk = tid >> 5;
            int c4 = (tid & 31) * 4;
            #pragma unroll
            for (int it = 0; it < 2; it++) {
                float4 v = *(const float4*)(Yn + (size_t)(k0 + kk + it * 8) * TV + c0 + c4);
                *(float4*)&Bs[kk + it * 8][c4] = v;
            }
        }
        __syncthreads();
        #pragma unroll
        for (int kk = 0; kk < BK; kk++) {
            float a[4], bv[8];
            *(float4*)a        = *(const float4*)&As[kk][trow];
            *(float4*)bv       = *(const float4*)&Bs[kk][tcol];
            *(float4*)(bv + 4) = *(const float4*)&Bs[kk][tcol + 4];
            #pragma unroll
            for (int i = 0; i < 4; i++)
                #pragma unroll
                for (int j = 0; j < 8; j++)
                    acc[i][j] = fmaf(a[i], bv[j], acc[i][j]);
        }
        __syncthreads();
    }

    const float rs = rsqrtf(1.f + 1e-5f);
    const float* Xn = x + (size_t)n * CC * TV;
    float* On = out + (size_t)n * OUTC * TV;
    #pragma unroll
    for (int i = 0; i < 4; i++) {
        int m = m0 + trow + i;
        float bi = bias[m], sc = gam[m] * rs, b2 = bb[m];
        const float* res = Xn + (size_t)m * TV + c0 + tcol;
        float4 r0 = *(const float4*)res;
        float4 r1 = *(const float4*)(res + 4);
        float vr[8];
        vr[0] = fmaxf((acc[i][0] + bi) * sc + b2 + r0.x, 0.f);
        vr[1] = fmaxf((acc[i][1] + bi) * sc + b2 + r0.y, 0.f);
        vr[2] = fmaxf((acc[i][2] + bi) * sc + b2 + r0.z, 0.f);
        vr[3] = fmaxf((acc[i][3] + bi) * sc + b2 + r0.w, 0.f);
        vr[4] = fmaxf((acc[i][4] + bi) * sc + b2 + r1.x, 0.f);
        vr[5] = fmaxf((acc[i][5] + bi) * sc + b2 + r1.y, 0.f);
        vr[6] = fmaxf((acc[i][6] + bi) * sc + b2 + r1.z, 0.f);
        vr[7] = fmaxf((acc[i][7] + bi) * sc + b2 + r1.w, 0.f);
        float* dst = On + (size_t)m * TV + c0 + tcol;
        *(float4*)dst       = *(float4*)vr;
        *(float4*)(dst + 4) = *(float4*)(vr + 4);
    }
}

// ---------------- launch ----------------
extern "C" void kernel_launch(void* const* d_in, const int* in_sizes, int n_in,
                              void* d_out, int out_size)
{
    const float* x       = (const float*)d_in[0];
    const float* A       = (const float*)d_in[1];
    const float* alpha   = (const float*)d_in[2];
    const float* beta    = (const float*)d_in[3];
    const float* pre_w   = (const float*)d_in[4];
    const float* pre_b   = (const float*)d_in[5];
    const float* pre_g   = (const float*)d_in[6];
    const float* pre_be  = (const float*)d_in[7];
    const float* conv1_w = (const float*)d_in[8];
    const float* conv1_b = (const float*)d_in[9];
    const float* conv2_w = (const float*)d_in[10];
    const float* conv2_b = (const float*)d_in[11];
    const float* post_w  = (const float*)d_in[12];
    const float* post_b  = (const float*)d_in[13];
    const float* bn_g    = (const float*)d_in[14];
    const float* bn_b    = (const float*)d_in[15];
    float* out = (float*)d_out;

    mean_kernel<<<NN * CC, 128>>>(x);
    attn_kernel<<<NN * KK, 256>>>(A, alpha, beta, conv1_w, conv1_b, conv2_w, conv2_b);
    gemm_pre_kernel<<<dim3(TV / BN, KM / BM, NN), 256>>>(x, pre_w, pre_b, pre_g, pre_be);
    agg_kernel<<<NN * KM, 128>>>();
    gemm_post_kernel<<<dim3(TV / BN, OUTC / BM, NN), 256>>>(x, post_w, post_b, bn_g, bn_b, out);
}

// round 3
// speedup vs baseline: 2.3054x; 2.3054x over previous
#include <cuda_runtime.h>
#include <cuda_bf16.h>
#include <cstdint>

#define NN   32
#define CC   256
#define TT   128
#define VV   25
#define KK   3
#define MIDC 64
#define KM   192
#define OUTC 256
#define TV   3200

// ---------------- scratch (device globals; no allocation) ----------------
__device__ float g_tmp[NN * CC * VV];
__device__ float g_afull[NN * KM * VV * VV];
__device__ float g_prex[NN * KM * TV];
__device__ float g_y[NN * KM * TV];

// ---------------- helpers ----------------
__device__ __forceinline__ uint32_t smem_u32(const void* p) {
    uint32_t a;
    asm("{ .reg .u64 t; cvta.to.shared.u64 t, %1; cvt.u32.u64 %0, t; }" : "=r"(a) : "l"(p));
    return a;
}

__device__ __forceinline__ void ldsm4(uint32_t* r, uint32_t addr) {
    asm volatile("ldmatrix.sync.aligned.m8n8.x4.shared.b16 {%0,%1,%2,%3}, [%4];"
                 : "=r"(r[0]), "=r"(r[1]), "=r"(r[2]), "=r"(r[3]) : "r"(addr));
}
__device__ __forceinline__ void ldsm4t(uint32_t* r, uint32_t addr) {
    asm volatile("ldmatrix.sync.aligned.m8n8.x4.trans.shared.b16 {%0,%1,%2,%3}, [%4];"
                 : "=r"(r[0]), "=r"(r[1]), "=r"(r[2]), "=r"(r[3]) : "r"(addr));
}
__device__ __forceinline__ void mma_bf16(float* d, const uint32_t* a, const uint32_t* b) {
    asm volatile(
        "mma.sync.aligned.m16n8k16.row.col.f32.bf16.bf16.f32 "
        "{%0,%1,%2,%3}, {%4,%5,%6,%7}, {%8,%9}, {%0,%1,%2,%3};"
        : "+f"(d[0]), "+f"(d[1]), "+f"(d[2]), "+f"(d[3])
        : "r"(a[0]), "r"(a[1]), "r"(a[2]), "r"(a[3]), "r"(b[0]), "r"(b[1]));
}

__device__ __forceinline__ uint32_t pack_bf(__nv_bfloat16 a, __nv_bfloat16 b) {
    return ((uint32_t)__bfloat16_as_ushort(b) << 16) | (uint32_t)__bfloat16_as_ushort(a);
}
__device__ __forceinline__ void split2(float x, float y, uint32_t& hi, uint32_t& lo) {
    __nv_bfloat16 hx = __float2bfloat16(x);
    __nv_bfloat16 hy = __float2bfloat16(y);
    float rx = x - __bfloat162float(hx);
    float ry = y - __bfloat162float(hy);
    hi = pack_bf(hx, hy);
    lo = pack_bf(__float2bfloat16(rx), __float2bfloat16(ry));
}

// ---------------- kernel 1: mean over T ----------------
__global__ void mean_kernel(const float* __restrict__ x) {
    int nc   = blockIdx.x;
    int lane = threadIdx.x & 31;
    int warp = threadIdx.x >> 5;
    __shared__ float red[4][VV];
    const float* base = x + (size_t)nc * (TT * VV);
    if (lane < VV) {
        float s = 0.f;
        for (int t = warp; t < TT; t += 4)
            s += base[t * VV + lane];
        red[warp][lane] = s;
    }
    __syncthreads();
    if (warp == 0 && lane < VV) {
        float tot = red[0][lane] + red[1][lane] + red[2][lane] + red[3][lane];
        g_tmp[nc * VV + lane] = tot * (1.0f / TT);
    }
}

// ---------------- kernel 2: attention / adjacency ----------------
__global__ __launch_bounds__(256) void attn_kernel(
    const float* __restrict__ A,  const float* __restrict__ alpha,
    const float* __restrict__ beta,
    const float* __restrict__ c1w, const float* __restrict__ c1b,
    const float* __restrict__ c2w, const float* __restrict__ c2b)
{
    int nk = blockIdx.x;
    int n  = nk / KK, k = nk % KK;
    int tid = threadIdx.x;

    __shared__ float tmp_s[CC * VV];
    __shared__ float x1_s[MIDC * VV];
    __shared__ float x2_s[MIDC * VV];
    __shared__ float g_s[VV * VV];

    const float* tsrc = g_tmp + n * CC * VV;
    for (int i = tid; i < CC * VV; i += 256) tmp_s[i] = tsrc[i];
    __syncthreads();

    int base = k * MIDC;
    for (int i = tid; i < MIDC * VV; i += 256) {
        int co = i / VV, a = i % VV;
        const float* w1 = c1w + (size_t)(base + co) * CC;
        const float* w2 = c2w + (size_t)(base + co) * CC;
        float a1 = c1b[base + co], a2 = c2b[base + co];
        #pragma unroll 8
        for (int c = 0; c < CC; c++) {
            float tvv = tmp_s[c * VV + a];
            a1 = fmaf(w1[c], tvv, a1);
            a2 = fmaf(w2[c], tvv, a2);
        }
        x1_s[i] = a1;
        x2_s[i] = a2;
    }
    __syncthreads();

    for (int i = tid; i < VV * VV; i += 256) {
        int a = i / VV, b = i % VV;
        float acc = 0.f;
        #pragma unroll 8
        for (int c = 0; c < MIDC; c++)
            acc = fmaf(x1_s[c * VV + a], x2_s[c * VV + b], acc);
        g_s[i] = acc;
    }
    __syncthreads();

    if (tid < VV) {
        int b = tid;
        float m = -1e30f;
        for (int a = 0; a < VV; a++) m = fmaxf(m, g_s[a * VV + b]);
        float ssum = 0.f;
        float e[VV];
        for (int a = 0; a < VV; a++) { e[a] = expf(g_s[a * VV + b] - m); ssum += e[a]; }
        float sc = beta[k] / ssum;
        for (int a = 0; a < VV; a++) g_s[a * VV + b] = e[a] * sc;
    }
    __syncthreads();

    float al = alpha[k];
    const float* Ak = A + k * VV * VV;
    float* outp = g_afull + (size_t)nk * MIDC * VV * VV;
    for (int i = tid; i < MIDC * VV * VV; i += 256) {
        int c = i / (VV * VV), r = i % (VV * VV);
        int a = r / VV, b = r % VV;
        outp[i] = tanhf(x1_s[c * VV + a] - x2_s[c * VV + b]) * al + Ak[r] + g_s[r];
    }
}

// ---------------- bf16x3 MMA GEMM ----------------
// C[m][tv] = W[m][k] * B[k][tv] per batch n, fused epilogue.
// CTA: 64 x 128 tile, BK=32, 8 warps (2x4), warp tile 32x32.
template <int KD, int NR, bool IS_POST>
__global__ __launch_bounds__(256) void gemm_mma(
    const float* __restrict__ Bglobal, const float* __restrict__ W,
    const float* __restrict__ bias, const float* __restrict__ gam,
    const float* __restrict__ bet,
    const float* __restrict__ resid, float* __restrict__ outp)
{
    __shared__ __align__(16) unsigned short As_h[64][40], As_l[64][40];
    __shared__ __align__(16) unsigned short Bs_h[32][136], Bs_l[32][136];

    const int tid  = threadIdx.x;
    const int lane = tid & 31;
    const int warp = tid >> 5;
    const int wm   = warp >> 2;   // 0..1
    const int wn   = warp & 3;    // 0..3
    const int n    = blockIdx.z;
    const int m0   = blockIdx.y * 64;
    const int c0   = blockIdx.x * 128;

    const float* Bn = (IS_POST ? (const float*)g_y : Bglobal) + (size_t)n * KD * TV;

    const int ar = tid >> 3;          // 0..31 (A rows, +32 second half)
    const int ac = (tid & 7) * 4;     // A k-cols
    const int br = tid >> 5;          // 0..7  (B k-rows, +8*i)
    const int bc = (tid & 31) * 4;    // B tv-cols

    float4 gA[2], gB[4];
    {
        const float* w0 = &W[(size_t)(m0 + ar) * KD + ac];
        gA[0] = *(const float4*)w0;
        gA[1] = *(const float4*)(w0 + (size_t)32 * KD);
        #pragma unroll
        for (int i = 0; i < 4; i++)
            gB[i] = *(const float4*)&Bn[(size_t)(br + i * 8) * TV + c0 + bc];
    }

    float acc[2][4][4];
    #pragma unroll
    for (int mi = 0; mi < 2; mi++)
        #pragma unroll
        for (int ni = 0; ni < 4; ni++)
            #pragma unroll
            for (int j = 0; j < 4; j++) acc[mi][ni][j] = 0.f;

    const uint32_t ash = smem_u32(As_h), asl = smem_u32(As_l);
    const uint32_t bsh = smem_u32(Bs_h), bsl = smem_u32(Bs_l);

    // ldmatrix per-thread address components
    const int a_row = (lane & 7) + ((lane >> 3) & 1) * 8;  // row within m16
    const int a_kof = (lane >> 4) * 8;                      // k-half
    const int b_kof = (lane & 7) + ((lane >> 3) & 1) * 8;  // k within 16
    const int b_nof = wn * 32 + (lane >> 4) * 8;           // n base (+pair*16)

    for (int k0 = 0; k0 < KD; k0 += 32) {
        // stage current tile to smem with hi/lo split
        #pragma unroll
        for (int i = 0; i < 2; i++) {
            float4 v = gA[i];
            int r = ar + i * 32;
            uint32_t h0, l0, h1, l1;
            split2(v.x, v.y, h0, l0);
            split2(v.z, v.w, h1, l1);
            *(uint32_t*)&As_h[r][ac]     = h0;
            *(uint32_t*)&As_h[r][ac + 2] = h1;
            *(uint32_t*)&As_l[r][ac]     = l0;
            *(uint32_t*)&As_l[r][ac + 2] = l1;
        }
        #pragma unroll
        for (int i = 0; i < 4; i++) {
            float4 v = gB[i];
            int r = br + i * 8;
            uint32_t h0, l0, h1, l1;
            split2(v.x, v.y, h0, l0);
            split2(v.z, v.w, h1, l1);
            *(uint32_t*)&Bs_h[r][bc]     = h0;
            *(uint32_t*)&Bs_h[r][bc + 2] = h1;
            *(uint32_t*)&Bs_l[r][bc]     = l0;
            *(uint32_t*)&Bs_l[r][bc + 2] = l1;
        }
        __syncthreads();

        // prefetch next tile
        if (k0 + 32 < KD) {
            const float* w0 = &W[(size_t)(m0 + ar) * KD + k0 + 32 + ac];
            gA[0] = *(const float4*)w0;
            gA[1] = *(const float4*)(w0 + (size_t)32 * KD);
            #pragma unroll
            for (int i = 0; i < 4; i++)
                gB[i] = *(const float4*)&Bn[(size_t)(k0 + 32 + br + i * 8) * TV + c0 + bc];
        }

        #pragma unroll
        for (int kk = 0; kk < 32; kk += 16) {
            uint32_t ah[2][4], al2[2][4], bh[4][2], bl[4][2];
            #pragma unroll
            for (int mi = 0; mi < 2; mi++) {
                uint32_t off = (uint32_t)((wm * 32 + mi * 16 + a_row) * 40 + kk + a_kof) * 2;
                ldsm4(ah[mi],  ash + off);
                ldsm4(al2[mi], asl + off);
            }
            #pragma unroll
            for (int p = 0; p < 2; p++) {
                uint32_t off = (uint32_t)((kk + b_kof) * 136 + b_nof + p * 16) * 2;
                uint32_t r[4];
                ldsm4t(r, bsh + off);
                bh[p * 2][0] = r[0]; bh[p * 2][1] = r[1];
                bh[p * 2 + 1][0] = r[2]; bh[p * 2 + 1][1] = r[3];
                ldsm4t(r, bsl + off);
                bl[p * 2][0] = r[0]; bl[p * 2][1] = r[1];
                bl[p * 2 + 1][0] = r[2]; bl[p * 2 + 1][1] = r[3];
            }
            #pragma unroll
            for (int mi = 0; mi < 2; mi++)
                #pragma unroll
                for (int ni = 0; ni < 4; ni++) {
                    mma_bf16(acc[mi][ni], ah[mi],  bh[ni]);
                    mma_bf16(acc[mi][ni], ah[mi],  bl[ni]);
                    mma_bf16(acc[mi][ni], al2[mi], bh[ni]);
                }
        }
        __syncthreads();
    }

    // fused epilogue
    const float rs = rsqrtf(1.f + 1e-5f);
    float* outbase = IS_POST ? outp : (float*)g_prex;
    #pragma unroll
    for (int mi = 0; mi < 2; mi++) {
        int mb = m0 + wm * 32 + mi * 16 + (lane >> 2);
        #pragma unroll
        for (int rr = 0; rr < 2; rr++) {
            int m = mb + rr * 8;
            float sc = gam[m] * rs, b1 = bias[m], b2 = bet[m];
            float* dst = outbase + ((size_t)n * NR + m) * TV + c0;
            const float* rsd = IS_POST ? resid + ((size_t)n * NR + m) * TV + c0 : nullptr;
            #pragma unroll
            for (int ni = 0; ni < 4; ni++) {
                int col = wn * 32 + ni * 8 + (lane & 3) * 2;
                float v0 = (acc[mi][ni][rr * 2 + 0] + b1) * sc + b2;
                float v1 = (acc[mi][ni][rr * 2 + 1] + b1) * sc + b2;
                if (IS_POST) { v0 += rsd[col]; v1 += rsd[col + 1]; }
                float2 o = make_float2(fmaxf(v0, 0.f), fmaxf(v1, 0.f));
                *(float2*)&dst[col] = o;
            }
        }
    }
}

// ---------------- kernel 4: graph aggregation ----------------
__global__ __launch_bounds__(128) void agg_kernel() {
    int idx = blockIdx.x;
    int tid = threadIdx.x;

    __shared__ float Af[VV * VV];
    __shared__ float px[TT * VV];
    __shared__ float ys[TT * VV];

    const float* Afg = g_afull + (size_t)idx * (VV * VV);
    for (int i = tid; i < VV * VV; i += 128) Af[i] = Afg[i];
    const float* pxg = g_prex + (size_t)idx * TV;
    for (int i = tid; i < TV; i += 128) px[i] = pxg[i];
    __syncthreads();

    int t = tid;
    float pr[VV];
    #pragma unroll
    for (int v = 0; v < VV; v++) pr[v] = px[t * VV + v];
    #pragma unroll
    for (int u = 0; u < VV; u++) {
        float accv = 0.f;
        #pragma unroll
        for (int v = 0; v < VV; v++)
            accv = fmaf(pr[v], Af[u * VV + v], accv);
        ys[t * VV + u] = accv;
    }
    __syncthreads();

    float* yg = g_y + (size_t)idx * TV;
    for (int i = tid; i < TV; i += 128) yg[i] = ys[i];
}

// ---------------- launch ----------------
extern "C" void kernel_launch(void* const* d_in, const int* in_sizes, int n_in,
                              void* d_out, int out_size)
{
    const float* x       = (const float*)d_in[0];
    const float* A       = (const float*)d_in[1];
    const float* alpha   = (const float*)d_in[2];
    const float* beta    = (const float*)d_in[3];
    const float* pre_w   = (const float*)d_in[4];
    const float* pre_b   = (const float*)d_in[5];
    const float* pre_g   = (const float*)d_in[6];
    const float* pre_be  = (const float*)d_in[7];
    const float* conv1_w = (const float*)d_in[8];
    const float* conv1_b = (const float*)d_in[9];
    const float* conv2_w = (const float*)d_in[10];
    const float* conv2_b = (const float*)d_in[11];
    const float* post_w  = (const float*)d_in[12];
    const float* post_b  = (const float*)d_in[13];
    const float* bn_g    = (const float*)d_in[14];
    const float* bn_b    = (const float*)d_in[15];
    float* out = (float*)d_out;

    mean_kernel<<<NN * CC, 128>>>(x);
    attn_kernel<<<NN * KK, 256>>>(A, alpha, beta, conv1_w, conv1_b, conv2_w, conv2_b);

    gemm_mma<CC, KM, false><<<dim3(TV / 128, KM / 64, NN), 256>>>(
        x, pre_w, pre_b, pre_g, pre_be, nullptr, nullptr);

    agg_kernel<<<NN * KM, 128>>>();

    gemm_mma<KM, OUTC, true><<<dim3(TV / 128, OUTC / 64, NN), 256>>>(
        nullptr, post_w, post_b, bn_g, bn_b, x, out);
}